// round 2
// baseline (speedup 1.0000x reference)
#include <cuda_runtime.h>
#include <cuda_bf16.h>
#include <math.h>
#include <stdint.h>

// Problem dims
#define Bn  2
#define Sn  2048
#define Dn  2048
#define Hn  16
#define DHn 128
#define Mn  (Bn*Sn)   // 4096

// Scratch (device globals: no allocations allowed)
__device__ __nv_bfloat16 g_Q[(size_t)Bn*Hn*Sn*DHn];   // [b,h,s,dh] bf16
__device__ __nv_bfloat16 g_K[(size_t)Bn*Hn*Sn*DHn];
__device__ __nv_bfloat16 g_V[(size_t)Bn*Hn*Sn*DHn];
__device__ float         g_attn[(size_t)Bn*Sn*Dn];    // [b,s,d] f32 (bf16-rounded)

__device__ __forceinline__ float2 bf2x(unsigned w) {
    __nv_bfloat162 h = *reinterpret_cast<__nv_bfloat162*>(&w);
    return __bfloat1622float2(h);
}

// ============================================================
// Tiled fp32 GEMM, C = A[M,K] * B[K,N], fused epilogue.
// MODE 0: rope -> bf16 -> g_Q   MODE 1: rope -> bf16 -> g_K
// MODE 2: cast -> bf16 -> g_V   MODE 3: A = g_attn, plain f32 -> outF
// ============================================================
template<int MODE>
__global__ void __launch_bounds__(256)
gemm_ep(const float* __restrict__ Ax, const float* __restrict__ Bw,
        float* __restrict__ outF)
{
    constexpr int BM = 128, BN = 128, BK = 8;
    constexpr int K = Dn, N = Dn;
    const float* Ap = (MODE == 3) ? g_attn : Ax;

    __shared__ float As[BK][BM];
    __shared__ float Bs[BK][BN];

    const int tid = threadIdx.x;
    const int tx = tid & 15;          // 0..15 -> 8 cols each
    const int ty = tid >> 4;          // 0..15 -> 8 rows each
    const int m0 = blockIdx.y * BM;
    const int n0 = blockIdx.x * BN;

    float acc[8][8];
    #pragma unroll
    for (int i = 0; i < 8; i++)
        #pragma unroll
        for (int j = 0; j < 8; j++) acc[i][j] = 0.f;

    const int aRow = tid >> 1;          // 0..127
    const int aCol = (tid & 1) * 4;     // 0 or 4
    const int bRow = tid >> 5;          // 0..7
    const int bCol = (tid & 31) * 4;    // 0..124

    const float* Aptr = Ap + (size_t)(m0 + aRow) * K + aCol;
    const float* Bptr = Bw + (size_t)bRow * N + n0 + bCol;

    for (int k0 = 0; k0 < K; k0 += BK) {
        float4 av = *reinterpret_cast<const float4*>(Aptr + k0);
        float4 bv = *reinterpret_cast<const float4*>(Bptr + (size_t)k0 * N);
        As[aCol + 0][aRow] = av.x;
        As[aCol + 1][aRow] = av.y;
        As[aCol + 2][aRow] = av.z;
        As[aCol + 3][aRow] = av.w;
        *reinterpret_cast<float4*>(&Bs[bRow][bCol]) = bv;
        __syncthreads();

        #pragma unroll
        for (int kk = 0; kk < BK; kk++) {
            float rm[8], rn[8];
            #pragma unroll
            for (int i = 0; i < 8; i++) rm[i] = As[kk][ty * 8 + i];
            #pragma unroll
            for (int j = 0; j < 8; j++) rn[j] = Bs[kk][tx * 8 + j];
            #pragma unroll
            for (int i = 0; i < 8; i++)
                #pragma unroll
                for (int j = 0; j < 8; j++)
                    acc[i][j] = fmaf(rm[i], rn[j], acc[i][j]);
        }
        __syncthreads();
    }

    // -------- epilogue --------
    if (MODE == 3) {
        #pragma unroll
        for (int i = 0; i < 8; i++) {
            const int r = m0 + ty * 8 + i;
            #pragma unroll
            for (int j = 0; j < 8; j++) {
                const int c = n0 + tx * 8 + j;
                outF[(size_t)r * N + c] = acc[i][j];
            }
        }
    } else if (MODE == 2) {
        #pragma unroll
        for (int i = 0; i < 8; i++) {
            const int r = m0 + ty * 8 + i;
            const int b = r >> 11;            // /S
            const int sIdx = r & (Sn - 1);
            #pragma unroll
            for (int j = 0; j < 8; j++) {
                const int c = n0 + tx * 8 + j;
                const int h = c >> 7;
                const int jd = c & (DHn - 1);
                g_V[((size_t)(b * Hn + h) * Sn + sIdx) * DHn + jd] =
                    __float2bfloat16(acc[i][j]);
            }
        }
    } else {
        __nv_bfloat16* outb = (MODE == 0) ? g_Q : g_K;
        const float LOG1E4 = 9.210340371976184f;
        #pragma unroll
        for (int i = 0; i < 8; i++) {
            const int r = m0 + ty * 8 + i;
            const int b = r >> 11;
            const int sIdx = r & (Sn - 1);
            #pragma unroll
            for (int j = 0; j < 8; j += 2) {
                const int c = n0 + tx * 8 + j;     // even
                const int h = c >> 7;
                const int jd = c & (DHn - 1);
                const int pi_ = jd >> 1;
                float inv = expf(-(float)(2 * pi_) / (float)DHn * LOG1E4);
                float ang = (float)sIdx * inv;
                float cs, sn;
                sincosf(ang, &sn, &cs);
                float e = acc[i][j], o = acc[i][j + 1];
                float re = e * cs - o * sn;
                float ro = e * sn + o * cs;
                size_t base = ((size_t)(b * Hn + h) * Sn + sIdx) * DHn + jd;
                outb[base]     = __float2bfloat16(re);
                outb[base + 1] = __float2bfloat16(ro);
            }
        }
    }
}

// ============================================================
// Two-pass causal flash attention.
// Block: 128 threads = 32 query rows; 4 threads ("quad") per row,
// each owns a 32-dim slice of DH=128. 64-key K/V tiles in smem.
// Pass 1: exact row max m and denominator l.
// Pass 2: p = bf16(exp(s-m)/l) (matches reference), accumulate p*V.
// ============================================================
__device__ __forceinline__ float dot32(const float* qv, const __nv_bfloat16* kp) {
    const uint4* kr = reinterpret_cast<const uint4*>(kp);
    float x = 0.f;
    #pragma unroll
    for (int c = 0; c < 4; c++) {
        uint4 u = kr[c];
        float2 f;
        f = bf2x(u.x); x = fmaf(qv[c*8+0], f.x, x); x = fmaf(qv[c*8+1], f.y, x);
        f = bf2x(u.y); x = fmaf(qv[c*8+2], f.x, x); x = fmaf(qv[c*8+3], f.y, x);
        f = bf2x(u.z); x = fmaf(qv[c*8+4], f.x, x); x = fmaf(qv[c*8+5], f.y, x);
        f = bf2x(u.w); x = fmaf(qv[c*8+6], f.x, x); x = fmaf(qv[c*8+7], f.y, x);
    }
    return x;
}

__global__ void __launch_bounds__(128)
flash_kernel()
{
    __shared__ __nv_bfloat16 Ks[64][DHn];
    __shared__ __nv_bfloat16 Vs[64][DHn];

    const int tid  = threadIdx.x;
    const int bh   = blockIdx.y;             // b*H + h
    const int q0   = blockIdx.x * 32;
    const int qrow = q0 + (tid >> 2);        // quad = 4 consecutive lanes
    const int sl   = (tid & 3) * 32;         // dim slice

    // load q slice (bf16 -> f32)
    float qv[32];
    {
        const uint4* qp = reinterpret_cast<const uint4*>(
            g_Q + ((size_t)bh * Sn + qrow) * DHn + sl);
        #pragma unroll
        for (int c = 0; c < 4; c++) {
            uint4 u = qp[c];
            float2 f;
            f = bf2x(u.x); qv[c*8+0] = f.x; qv[c*8+1] = f.y;
            f = bf2x(u.y); qv[c*8+2] = f.x; qv[c*8+3] = f.y;
            f = bf2x(u.z); qv[c*8+4] = f.x; qv[c*8+5] = f.y;
            f = bf2x(u.w); qv[c*8+6] = f.x; qv[c*8+7] = f.y;
        }
    }

    const int nT = (q0 + 32 + 63) / 64;
    const float scale = 0.08838834764831845f;   // 1/sqrt(128)

    const uint4* Kg = reinterpret_cast<const uint4*>(g_K + (size_t)bh * Sn * DHn);
    const uint4* Vg = reinterpret_cast<const uint4*>(g_V + (size_t)bh * Sn * DHn);
    uint4* KsV = reinterpret_cast<uint4*>(&Ks[0][0]);
    uint4* VsV = reinterpret_cast<uint4*>(&Vs[0][0]);

    // ---- pass 1: m, l ----
    float m = -INFINITY, l = 0.f;
    for (int kt = 0; kt < nT; kt++) {
        for (int i2 = tid; i2 < 1024; i2 += 128) KsV[i2] = Kg[kt * 1024 + i2];
        __syncthreads();
        const bool full = (kt * 64 + 63 <= qrow);
        if (full) {
            #pragma unroll 4
            for (int kk = 0; kk < 64; kk++) {
                float sc = dot32(qv, &Ks[kk][sl]);
                sc += __shfl_xor_sync(0xffffffffu, sc, 1);
                sc += __shfl_xor_sync(0xffffffffu, sc, 2);
                sc *= scale;
                float mn = fmaxf(m, sc);
                l = l * __expf(m - mn) + __expf(sc - mn);
                m = mn;
            }
        } else {
            #pragma unroll 4
            for (int kk = 0; kk < 64; kk++) {
                float sc = dot32(qv, &Ks[kk][sl]);
                sc += __shfl_xor_sync(0xffffffffu, sc, 1);
                sc += __shfl_xor_sync(0xffffffffu, sc, 2);
                sc *= scale;
                int key = kt * 64 + kk;
                if (key <= qrow) {
                    float mn = fmaxf(m, sc);
                    l = l * __expf(m - mn) + __expf(sc - mn);
                    m = mn;
                }
            }
        }
        __syncthreads();
    }
    const float inv_l = 1.0f / l;

    // ---- pass 2: accumulate bf16(p) * V ----
    float acc[32];
    #pragma unroll
    for (int i = 0; i < 32; i++) acc[i] = 0.f;

    for (int kt = 0; kt < nT; kt++) {
        for (int i2 = tid; i2 < 1024; i2 += 128) {
            KsV[i2] = Kg[kt * 1024 + i2];
            VsV[i2] = Vg[kt * 1024 + i2];
        }
        __syncthreads();
        #pragma unroll 2
        for (int kk = 0; kk < 64; kk++) {
            float sc = dot32(qv, &Ks[kk][sl]);
            sc += __shfl_xor_sync(0xffffffffu, sc, 1);
            sc += __shfl_xor_sync(0xffffffffu, sc, 2);
            sc *= scale;
            int key = kt * 64 + kk;
            if (key <= qrow) {
                float p  = __expf(sc - m) * inv_l;
                float pf = __bfloat162float(__float2bfloat16(p));
                const uint4* vr = reinterpret_cast<const uint4*>(&Vs[kk][sl]);
                #pragma unroll
                for (int c = 0; c < 4; c++) {
                    uint4 u = vr[c];
                    float2 f;
                    f = bf2x(u.x); acc[c*8+0]=fmaf(pf,f.x,acc[c*8+0]); acc[c*8+1]=fmaf(pf,f.y,acc[c*8+1]);
                    f = bf2x(u.y); acc[c*8+2]=fmaf(pf,f.x,acc[c*8+2]); acc[c*8+3]=fmaf(pf,f.y,acc[c*8+3]);
                    f = bf2x(u.z); acc[c*8+4]=fmaf(pf,f.x,acc[c*8+4]); acc[c*8+5]=fmaf(pf,f.y,acc[c*8+5]);
                    f = bf2x(u.w); acc[c*8+6]=fmaf(pf,f.x,acc[c*8+6]); acc[c*8+7]=fmaf(pf,f.y,acc[c*8+7]);
                }
            }
        }
        __syncthreads();
    }

    // write attn (round through bf16, matching reference)
    const int b = bh >> 4, h = bh & 15;
    float* dst = g_attn + ((size_t)(b * Sn + qrow)) * Dn + h * DHn + sl;
    #pragma unroll
    for (int i = 0; i < 32; i++)
        dst[i] = __bfloat162float(__float2bfloat16(acc[i]));
}

// ============================================================
extern "C" void kernel_launch(void* const* d_in, const int* in_sizes, int n_in,
                              void* d_out, int out_size)
{
    const float* x  = (const float*)d_in[0];
    const float* wq = (const float*)d_in[1];
    const float* wk = (const float*)d_in[2];
    const float* wv = (const float*)d_in[3];
    const float* wo = (const float*)d_in[4];
    float* out = (float*)d_out;

    dim3 gg(Dn / 128, Mn / 128);
    dim3 gb(256);
    gemm_ep<0><<<gg, gb>>>(x, wq, nullptr);   // Q (rope, bf16)
    gemm_ep<1><<<gg, gb>>>(x, wk, nullptr);   // K (rope, bf16)
    gemm_ep<2><<<gg, gb>>>(x, wv, nullptr);   // V (bf16)
    flash_kernel<<<dim3(Sn / 32, Bn * Hn), 128>>>();
    gemm_ep<3><<<gg, gb>>>(nullptr, wo, out); // out = attn @ wo
}

// round 5
// speedup vs baseline: 1.1660x; 1.1660x over previous
#include <cuda_runtime.h>
#include <cuda_bf16.h>
#include <cuda_fp16.h>
#include <math.h>
#include <stdint.h>

// Problem dims
#define Bn  2
#define Sn  2048
#define Dn  2048
#define Hn  16
#define DHn 128
#define Mn  (Bn*Sn)   // 4096

typedef __nv_bfloat16 bf16;
typedef __nv_bfloat162 bf162;

// ---------------- scratch (device globals; no allocation allowed) ----------
__device__ __half g_xhi[(size_t)Mn*Dn];
__device__ __half g_xlo[(size_t)Mn*Dn];
__device__ __half g_whi[4][(size_t)Dn*Dn];   // wq, wk, wv, wo
__device__ __half g_wlo[4][(size_t)Dn*Dn];
__device__ bf16 g_Q[(size_t)Bn*Hn*Sn*DHn];   // [b,h,s,dh]
__device__ bf16 g_K[(size_t)Bn*Hn*Sn*DHn];
__device__ bf16 g_V[(size_t)Bn*Hn*Sn*DHn];
__device__ __half g_attnb[(size_t)Mn*Dn];    // [b,s,d] fp16 (holds exact bf16 values)
__device__ float2 g_rope[(size_t)Sn*64];     // (cos, sin)

__device__ __forceinline__ float2 bf2x(unsigned w) {
    bf162 h = *reinterpret_cast<bf162*>(&w);
    return __bfloat1622float2(h);
}
__device__ __forceinline__ unsigned saddr(const void* p) {
    return (unsigned)__cvta_generic_to_shared(p);
}

// ---------------- helpers ---------------------------------------------------
__global__ void split_kernel(const float* __restrict__ s,
                             __half* __restrict__ hi, __half* __restrict__ lo, int n4)
{
    int i = blockIdx.x * blockDim.x + threadIdx.x;
    if (i >= n4) return;
    float4 v = reinterpret_cast<const float4*>(s)[i];
    __half h0 = __float2half(v.x), h1 = __float2half(v.y);
    __half h2 = __float2half(v.z), h3 = __float2half(v.w);
    __half2 H0; H0.x = h0; H0.y = h1;
    __half2 H1; H1.x = h2; H1.y = h3;
    reinterpret_cast<__half2*>(hi)[2*i]   = H0;
    reinterpret_cast<__half2*>(hi)[2*i+1] = H1;
    __half2 L0, L1;
    L0.x = __float2half(v.x - __half2float(h0));
    L0.y = __float2half(v.y - __half2float(h1));
    L1.x = __float2half(v.z - __half2float(h2));
    L1.y = __float2half(v.w - __half2float(h3));
    reinterpret_cast<__half2*>(lo)[2*i]   = L0;
    reinterpret_cast<__half2*>(lo)[2*i+1] = L1;
}

__global__ void rope_tab_kernel()
{
    int idx = blockIdx.x * blockDim.x + threadIdx.x;   // s*64 + i
    if (idx >= Sn * 64) return;
    int s = idx >> 6, i = idx & 63;
    const float LOG1E4 = 9.210340371976184f;
    float inv = expf(-((float)(2 * i) / 128.0f) * LOG1E4);
    float ang = (float)s * inv;
    float sn, cs;
    sincosf(ang, &sn, &cs);
    g_rope[idx] = make_float2(cs, sn);
}

// ---------------- mma primitives -------------------------------------------
__device__ __forceinline__ void ldmA(unsigned &r0, unsigned &r1, unsigned &r2, unsigned &r3, unsigned a) {
    asm volatile("ldmatrix.sync.aligned.m8n8.x4.shared.b16 {%0,%1,%2,%3}, [%4];"
                 : "=r"(r0), "=r"(r1), "=r"(r2), "=r"(r3) : "r"(a));
}
__device__ __forceinline__ void ldmBT(unsigned &r0, unsigned &r1, unsigned &r2, unsigned &r3, unsigned a) {
    asm volatile("ldmatrix.sync.aligned.m8n8.x4.trans.shared.b16 {%0,%1,%2,%3}, [%4];"
                 : "=r"(r0), "=r"(r1), "=r"(r2), "=r"(r3) : "r"(a));
}
__device__ __forceinline__ void mma16816(float* d, const unsigned* a, const unsigned* b) {
    asm volatile("mma.sync.aligned.m16n8k16.row.col.f32.f16.f16.f32 "
                 "{%0,%1,%2,%3}, {%4,%5,%6,%7}, {%8,%9}, {%0,%1,%2,%3};"
                 : "+f"(d[0]), "+f"(d[1]), "+f"(d[2]), "+f"(d[3])
                 : "r"(a[0]), "r"(a[1]), "r"(a[2]), "r"(a[3]), "r"(b[0]), "r"(b[1]));
}

// ---------------- fp16 tensor-core GEMM with fused epilogue -----------------
// C[M,N] = sum_ph A_ph[M,K] @ B_ph[K,N]
// Accumulator DRAIN every 4 k-tiles (K=128) into an fp32 register sum to
// suppress tensor-core truncation bias in long chained accumulations.
// MODE 0: rope->bf16->g_Q   MODE 1: rope->bf16->g_K
// MODE 2: bf16->g_V          MODE 3: f32->outF
template<int MODE>
__global__ void __launch_bounds__(256)
gemm_mma(const __half* __restrict__ A0, const __half* __restrict__ B0,
         const __half* __restrict__ A1, const __half* __restrict__ B1,
         const __half* __restrict__ A2, const __half* __restrict__ B2,
         int nPhase, float* __restrict__ outF)
{
    constexpr int K = Dn, N = Dn;
    constexpr int LDA = 40, LDB = 136;
    __shared__ __half As[128 * LDA];
    __shared__ __half Bs[32 * LDB];

    const int tid = threadIdx.x;
    const int wid = tid >> 5, lane = tid & 31;
    const int wm = wid & 3, wn = wid >> 2;       // 4 x 2 warps
    const int m0 = blockIdx.y * 128, n0 = blockIdx.x * 128;

    float d[2][8][4];     // HMMA accumulator (short chains)
    float sum[2][8][4];   // fp32 master accumulator (RN adds)
    #pragma unroll
    for (int mf = 0; mf < 2; mf++)
        #pragma unroll
        for (int nf = 0; nf < 8; nf++)
            #pragma unroll
            for (int e = 0; e < 4; e++) { d[mf][nf][e] = 0.f; sum[mf][nf][e] = 0.f; }

    const int arow = tid >> 1, acol = (tid & 1) * 16;
    const int brow = tid >> 3, bcol = (tid & 7) * 16;

    const __half* APh[3] = {A0, A1, A2};
    const __half* BPh[3] = {B0, B1, B2};

    for (int ph = 0; ph < nPhase; ph++) {
        const __half* Ag = APh[ph] + (size_t)(m0 + arow) * K + acol;
        const __half* Bg = BPh[ph] + (size_t)brow * N + n0 + bcol;
        int ktIdx = 0;
        for (int kt = 0; kt < K; kt += 32, ktIdx++) {
            uint4 a0v = *reinterpret_cast<const uint4*>(Ag + kt);
            uint4 a1v = *reinterpret_cast<const uint4*>(Ag + kt + 8);
            uint4 b0v = *reinterpret_cast<const uint4*>(Bg + (size_t)kt * N);
            uint4 b1v = *reinterpret_cast<const uint4*>(Bg + (size_t)kt * N + 8);
            __syncthreads();
            *reinterpret_cast<uint4*>(As + arow * LDA + acol)     = a0v;
            *reinterpret_cast<uint4*>(As + arow * LDA + acol + 8) = a1v;
            *reinterpret_cast<uint4*>(Bs + brow * LDB + bcol)     = b0v;
            *reinterpret_cast<uint4*>(Bs + brow * LDB + bcol + 8) = b1v;
            __syncthreads();

            #pragma unroll
            for (int kk = 0; kk < 32; kk += 16) {
                unsigned a[2][4];
                #pragma unroll
                for (int mf = 0; mf < 2; mf++) {
                    const __half* p = As + (wm * 32 + mf * 16 + (lane & 15)) * LDA
                                         + kk + (lane >> 4) * 8;
                    ldmA(a[mf][0], a[mf][1], a[mf][2], a[mf][3], saddr(p));
                }
                unsigned bfr[8][2];
                #pragma unroll
                for (int nq = 0; nq < 4; nq++) {
                    const __half* p = Bs + (kk + (lane & 15)) * LDB
                                         + wn * 64 + nq * 16 + (lane >> 4) * 8;
                    unsigned r0, r1, r2, r3;
                    ldmBT(r0, r1, r2, r3, saddr(p));
                    bfr[nq*2][0] = r0; bfr[nq*2][1] = r1;
                    bfr[nq*2+1][0] = r2; bfr[nq*2+1][1] = r3;
                }
                #pragma unroll
                for (int mf = 0; mf < 2; mf++)
                    #pragma unroll
                    for (int nf = 0; nf < 8; nf++)
                        mma16816(d[mf][nf], a[mf], bfr[nf]);
            }

            // drain every 4 k-tiles: bound tensor-core truncation-bias chains
            if ((ktIdx & 3) == 3) {
                #pragma unroll
                for (int mf = 0; mf < 2; mf++)
                    #pragma unroll
                    for (int nf = 0; nf < 8; nf++)
                        #pragma unroll
                        for (int e = 0; e < 4; e++) {
                            sum[mf][nf][e] += d[mf][nf][e];
                            d[mf][nf][e] = 0.f;
                        }
            }
        }
    }

    // ---------------- epilogue ----------------
    const int lr = lane >> 2;
    const int lc = (lane & 3) * 2;
    #pragma unroll
    for (int mf = 0; mf < 2; mf++) {
        #pragma unroll
        for (int nf = 0; nf < 8; nf++) {
            float* dd = sum[mf][nf];
            const int row0 = m0 + wm * 32 + mf * 16 + lr;
            const int col  = n0 + wn * 64 + nf * 8 + lc;
            #pragma unroll
            for (int half = 0; half < 2; half++) {
                const int row = row0 + half * 8;
                const float e = dd[half*2], o = dd[half*2 + 1];
                if (MODE == 3) {
                    *reinterpret_cast<float2*>(outF + (size_t)row * N + col) =
                        make_float2(e, o);
                } else {
                    const int b = row >> 11, s = row & (Sn - 1);
                    const int h = col >> 7, jd = col & (DHn - 1);
                    bf16* dst = (MODE == 0) ? g_Q : (MODE == 1) ? g_K : g_V;
                    bf162 val;
                    if (MODE == 2) {
                        val.x = __float2bfloat16(e);
                        val.y = __float2bfloat16(o);
                    } else {
                        float2 cssn = g_rope[s * 64 + (jd >> 1)];
                        val.x = __float2bfloat16(e * cssn.x - o * cssn.y);
                        val.y = __float2bfloat16(e * cssn.y + o * cssn.x);
                    }
                    *reinterpret_cast<bf162*>(
                        dst + ((size_t)(b * Hn + h) * Sn + s) * DHn + jd) = val;
                }
            }
        }
    }
}

// ============================================================
// Two-pass causal flash attention (scalar; known-good numerics)
// ============================================================
__device__ __forceinline__ float dot32(const float* qv, const bf16* kp) {
    const uint4* kr = reinterpret_cast<const uint4*>(kp);
    float x = 0.f;
    #pragma unroll
    for (int c = 0; c < 4; c++) {
        uint4 u = kr[c];
        float2 f;
        f = bf2x(u.x); x = fmaf(qv[c*8+0], f.x, x); x = fmaf(qv[c*8+1], f.y, x);
        f = bf2x(u.y); x = fmaf(qv[c*8+2], f.x, x); x = fmaf(qv[c*8+3], f.y, x);
        f = bf2x(u.z); x = fmaf(qv[c*8+4], f.x, x); x = fmaf(qv[c*8+5], f.y, x);
        f = bf2x(u.w); x = fmaf(qv[c*8+6], f.x, x); x = fmaf(qv[c*8+7], f.y, x);
    }
    return x;
}

__global__ void __launch_bounds__(128)
flash_kernel()
{
    __shared__ bf16 Ks[64][DHn];
    __shared__ bf16 Vs[64][DHn];

    const int tid  = threadIdx.x;
    const int bh   = blockIdx.y;
    const int q0   = blockIdx.x * 32;
    const int qrow = q0 + (tid >> 2);
    const int sl   = (tid & 3) * 32;

    float qv[32];
    {
        const uint4* qp = reinterpret_cast<const uint4*>(
            g_Q + ((size_t)bh * Sn + qrow) * DHn + sl);
        #pragma unroll
        for (int c = 0; c < 4; c++) {
            uint4 u = qp[c];
            float2 f;
            f = bf2x(u.x); qv[c*8+0] = f.x; qv[c*8+1] = f.y;
            f = bf2x(u.y); qv[c*8+2] = f.x; qv[c*8+3] = f.y;
            f = bf2x(u.z); qv[c*8+4] = f.x; qv[c*8+5] = f.y;
            f = bf2x(u.w); qv[c*8+6] = f.x; qv[c*8+7] = f.y;
        }
    }

    const int nT = (q0 + 32 + 63) / 64;
    const float scale = 0.08838834764831845f;

    const uint4* Kg = reinterpret_cast<const uint4*>(g_K + (size_t)bh * Sn * DHn);
    const uint4* Vg = reinterpret_cast<const uint4*>(g_V + (size_t)bh * Sn * DHn);
    uint4* KsV = reinterpret_cast<uint4*>(&Ks[0][0]);
    uint4* VsV = reinterpret_cast<uint4*>(&Vs[0][0]);

    float m = -INFINITY, l = 0.f;
    for (int kt = 0; kt < nT; kt++) {
        for (int i2 = tid; i2 < 1024; i2 += 128) KsV[i2] = Kg[kt * 1024 + i2];
        __syncthreads();
        const bool full = (kt * 64 + 63 <= qrow);
        if (full) {
            #pragma unroll 4
            for (int kk = 0; kk < 64; kk++) {
                float sc = dot32(qv, &Ks[kk][sl]);
                sc += __shfl_xor_sync(0xffffffffu, sc, 1);
                sc += __shfl_xor_sync(0xffffffffu, sc, 2);
                sc *= scale;
                float mn = fmaxf(m, sc);
                l = l * __expf(m - mn) + __expf(sc - mn);
                m = mn;
            }
        } else {
            #pragma unroll 4
            for (int kk = 0; kk < 64; kk++) {
                float sc = dot32(qv, &Ks[kk][sl]);
                sc += __shfl_xor_sync(0xffffffffu, sc, 1);
                sc += __shfl_xor_sync(0xffffffffu, sc, 2);
                sc *= scale;
                int key = kt * 64 + kk;
                if (key <= qrow) {
                    float mn = fmaxf(m, sc);
                    l = l * __expf(m - mn) + __expf(sc - mn);
                    m = mn;
                }
            }
        }
        __syncthreads();
    }
    const float inv_l = 1.0f / l;

    float acc[32];
    #pragma unroll
    for (int i = 0; i < 32; i++) acc[i] = 0.f;

    for (int kt = 0; kt < nT; kt++) {
        for (int i2 = tid; i2 < 1024; i2 += 128) {
            KsV[i2] = Kg[kt * 1024 + i2];
            VsV[i2] = Vg[kt * 1024 + i2];
        }
        __syncthreads();
        #pragma unroll 2
        for (int kk = 0; kk < 64; kk++) {
            float sc = dot32(qv, &Ks[kk][sl]);
            sc += __shfl_xor_sync(0xffffffffu, sc, 1);
            sc += __shfl_xor_sync(0xffffffffu, sc, 2);
            sc *= scale;
            int key = kt * 64 + kk;
            if (key <= qrow) {
                float p  = __expf(sc - m) * inv_l;
                float pf = __bfloat162float(__float2bfloat16(p));
                const uint4* vr = reinterpret_cast<const uint4*>(&Vs[kk][sl]);
                #pragma unroll
                for (int c = 0; c < 4; c++) {
                    uint4 u = vr[c];
                    float2 f;
                    f = bf2x(u.x); acc[c*8+0]=fmaf(pf,f.x,acc[c*8+0]); acc[c*8+1]=fmaf(pf,f.y,acc[c*8+1]);
                    f = bf2x(u.y); acc[c*8+2]=fmaf(pf,f.x,acc[c*8+2]); acc[c*8+3]=fmaf(pf,f.y,acc[c*8+3]);
                    f = bf2x(u.z); acc[c*8+4]=fmaf(pf,f.x,acc[c*8+4]); acc[c*8+5]=fmaf(pf,f.y,acc[c*8+5]);
                    f = bf2x(u.w); acc[c*8+6]=fmaf(pf,f.x,acc[c*8+6]); acc[c*8+7]=fmaf(pf,f.y,acc[c*8+7]);
                }
            }
        }
        __syncthreads();
    }

    // write attn rounded through bf16 (matching reference), stored as fp16 (exact)
    const int b = bh >> 4, h = bh & 15;
    __half* dst = g_attnb + ((size_t)(b * Sn + qrow)) * Dn + h * DHn + sl;
    #pragma unroll
    for (int i = 0; i < 32; i += 2) {
        __half2 v2;
        v2.x = __float2half(__bfloat162float(__float2bfloat16(acc[i])));
        v2.y = __float2half(__bfloat162float(__float2bfloat16(acc[i+1])));
        *reinterpret_cast<__half2*>(dst + i) = v2;
    }
}

// ============================================================
extern "C" void kernel_launch(void* const* d_in, const int* in_sizes, int n_in,
                              void* d_out, int out_size)
{
    const float* x  = (const float*)d_in[0];
    const float* w[4] = {(const float*)d_in[1], (const float*)d_in[2],
                         (const float*)d_in[3], (const float*)d_in[4]};
    float* out = (float*)d_out;

    __half *xhi, *xlo, *whi[4], *wlo[4], *attnb;
    cudaGetSymbolAddress((void**)&xhi, g_xhi);
    cudaGetSymbolAddress((void**)&xlo, g_xlo);
    cudaGetSymbolAddress((void**)&attnb, g_attnb);
    {
        __half *base_hi, *base_lo;
        cudaGetSymbolAddress((void**)&base_hi, g_whi);
        cudaGetSymbolAddress((void**)&base_lo, g_wlo);
        for (int i = 0; i < 4; i++) {
            whi[i] = base_hi + (size_t)i * Dn * Dn;
            wlo[i] = base_lo + (size_t)i * Dn * Dn;
        }
    }

    // split inputs into fp16 hi/lo
    {
        int n4 = Mn * Dn / 4;
        split_kernel<<<(n4 + 255) / 256, 256>>>(x, xhi, xlo, n4);
        int m4 = Dn * Dn / 4;
        for (int i = 0; i < 4; i++)
            split_kernel<<<(m4 + 255) / 256, 256>>>(w[i], whi[i], wlo[i], m4);
    }
    rope_tab_kernel<<<(Sn * 64 + 255) / 256, 256>>>();

    dim3 gg(Dn / 128, Mn / 128);
    // Q/K/V: A@B = xhi@whi + xlo@whi + xhi@wlo
    gemm_mma<0><<<gg, 256>>>(xhi, whi[0], xlo, whi[0], xhi, wlo[0], 3, nullptr);
    gemm_mma<1><<<gg, 256>>>(xhi, whi[1], xlo, whi[1], xhi, wlo[1], 3, nullptr);
    gemm_mma<2><<<gg, 256>>>(xhi, whi[2], xlo, whi[2], xhi, wlo[2], 3, nullptr);

    flash_kernel<<<dim3(Sn / 32, Bn * Hn), 128>>>();

    // out = attnb @ wo   (attnb exact, wo split -> 2 phases)
    gemm_mma<3><<<gg, 256>>>(attnb, whi[3], attnb, wlo[3], nullptr, nullptr, 2, out);
}

// round 6
// speedup vs baseline: 1.2809x; 1.0985x over previous
#include <cuda_runtime.h>
#include <cuda_bf16.h>
#include <cuda_fp16.h>
#include <math.h>
#include <stdint.h>

// Problem dims
#define Bn  2
#define Sn  2048
#define Dn  2048
#define Hn  16
#define DHn 128
#define Mn  (Bn*Sn)   // 4096

typedef __nv_bfloat16 bf16;
typedef __nv_bfloat162 bf162;

// ---------------- scratch (device globals; no allocation allowed) ----------
__device__ __half g_xhi[(size_t)Mn*Dn];
__device__ __half g_xlo[(size_t)Mn*Dn];
__device__ __half g_whi[4][(size_t)Dn*Dn];   // wq, wk, wv, wo
__device__ __half g_wlo[4][(size_t)Dn*Dn];
__device__ bf16 g_Q[(size_t)Bn*Hn*Sn*DHn];   // [b,h,s,dh]
__device__ bf16 g_K[(size_t)Bn*Hn*Sn*DHn];
__device__ bf16 g_V[(size_t)Bn*Hn*Sn*DHn];
__device__ __half g_attnb[(size_t)Mn*Dn];    // [b,s,d] fp16 (holds exact bf16 values)
__device__ float2 g_rope[(size_t)Sn*64];     // (cos, sin)

__device__ __forceinline__ float2 bf2x(unsigned w) {
    bf162 h = *reinterpret_cast<bf162*>(&w);
    return __bfloat1622float2(h);
}
__device__ __forceinline__ unsigned saddr(const void* p) {
    return (unsigned)__cvta_generic_to_shared(p);
}

// ---------------- cp.async helpers -----------------------------------------
__device__ __forceinline__ void cpa16(unsigned s, const void* g) {
    asm volatile("cp.async.cg.shared.global [%0], [%1], 16;\n" :: "r"(s), "l"(g));
}
__device__ __forceinline__ void cpcommit() {
    asm volatile("cp.async.commit_group;\n" ::);
}
template<int NW> __device__ __forceinline__ void cpwait() {
    asm volatile("cp.async.wait_group %0;\n" :: "n"(NW));
}

// ---------------- helpers ---------------------------------------------------
__global__ void split_kernel(const float* __restrict__ s,
                             __half* __restrict__ hi, __half* __restrict__ lo, int n4)
{
    int i = blockIdx.x * blockDim.x + threadIdx.x;
    if (i >= n4) return;
    float4 v = reinterpret_cast<const float4*>(s)[i];
    __half h0 = __float2half(v.x), h1 = __float2half(v.y);
    __half h2 = __float2half(v.z), h3 = __float2half(v.w);
    __half2 H0; H0.x = h0; H0.y = h1;
    __half2 H1; H1.x = h2; H1.y = h3;
    reinterpret_cast<__half2*>(hi)[2*i]   = H0;
    reinterpret_cast<__half2*>(hi)[2*i+1] = H1;
    __half2 L0, L1;
    L0.x = __float2half(v.x - __half2float(h0));
    L0.y = __float2half(v.y - __half2float(h1));
    L1.x = __float2half(v.z - __half2float(h2));
    L1.y = __float2half(v.w - __half2float(h3));
    reinterpret_cast<__half2*>(lo)[2*i]   = L0;
    reinterpret_cast<__half2*>(lo)[2*i+1] = L1;
}

__global__ void rope_tab_kernel()
{
    int idx = blockIdx.x * blockDim.x + threadIdx.x;   // s*64 + i
    if (idx >= Sn * 64) return;
    int s = idx >> 6, i = idx & 63;
    const float LOG1E4 = 9.210340371976184f;
    float inv = expf(-((float)(2 * i) / 128.0f) * LOG1E4);
    float ang = (float)s * inv;
    float sn, cs;
    sincosf(ang, &sn, &cs);
    g_rope[idx] = make_float2(cs, sn);
}

// ---------------- mma primitives -------------------------------------------
__device__ __forceinline__ void ldmA(unsigned &r0, unsigned &r1, unsigned &r2, unsigned &r3, unsigned a) {
    asm volatile("ldmatrix.sync.aligned.m8n8.x4.shared.b16 {%0,%1,%2,%3}, [%4];"
                 : "=r"(r0), "=r"(r1), "=r"(r2), "=r"(r3) : "r"(a));
}
__device__ __forceinline__ void ldmBT(unsigned &r0, unsigned &r1, unsigned &r2, unsigned &r3, unsigned a) {
    asm volatile("ldmatrix.sync.aligned.m8n8.x4.trans.shared.b16 {%0,%1,%2,%3}, [%4];"
                 : "=r"(r0), "=r"(r1), "=r"(r2), "=r"(r3) : "r"(a));
}
__device__ __forceinline__ void mma16816(float* d, const unsigned* a, const unsigned* b) {
    asm volatile("mma.sync.aligned.m16n8k16.row.col.f32.f16.f16.f32 "
                 "{%0,%1,%2,%3}, {%4,%5,%6,%7}, {%8,%9}, {%0,%1,%2,%3};"
                 : "+f"(d[0]), "+f"(d[1]), "+f"(d[2]), "+f"(d[3])
                 : "r"(a[0]), "r"(a[1]), "r"(a[2]), "r"(a[3]), "r"(b[0]), "r"(b[1]));
}

// ---------------- fp16 tensor-core GEMM, cp.async 2-stage pipeline ----------
// C[M,N] = sum_ph A_ph[M,K] @ B_ph[K,N]
// Accumulator DRAIN every 4 k-tiles into fp32 (suppresses HMMA chain bias).
// MODE 0: rope->bf16->g_Q   MODE 1: rope->bf16->g_K
// MODE 2: bf16->g_V          MODE 3: f32->outF
template<int MODE>
__global__ void __launch_bounds__(256)
gemm_mma(const __half* __restrict__ A0, const __half* __restrict__ B0,
         const __half* __restrict__ A1, const __half* __restrict__ B1,
         const __half* __restrict__ A2, const __half* __restrict__ B2,
         int nPhase, float* __restrict__ outF)
{
    constexpr int K = Dn, N = Dn;
    constexpr int LDA = 40, LDB = 136;
    __shared__ __half As[2][128 * LDA];
    __shared__ __half Bs[2][32 * LDB];

    const int tid = threadIdx.x;
    const int wid = tid >> 5, lane = tid & 31;
    const int wm = wid & 3, wn = wid >> 2;       // 4 x 2 warps
    const int m0 = blockIdx.y * 128, n0 = blockIdx.x * 128;

    float d[2][8][4];     // HMMA accumulator (short chains)
    float sum[2][8][4];   // fp32 master accumulator (RN adds)
    #pragma unroll
    for (int mf = 0; mf < 2; mf++)
        #pragma unroll
        for (int nf = 0; nf < 8; nf++)
            #pragma unroll
            for (int e = 0; e < 4; e++) { d[mf][nf][e] = 0.f; sum[mf][nf][e] = 0.f; }

    // loading layout: A 16 halves/thread/tile, B 16 halves/thread/tile
    const int arow = tid >> 1, acol = (tid & 1) * 16;
    const int brow = tid >> 3, bcol = (tid & 7) * 16;

    unsigned sA[2], sB[2];
    #pragma unroll
    for (int b = 0; b < 2; b++) {
        sA[b] = saddr(&As[b][arow * LDA + acol]);
        sB[b] = saddr(&Bs[b][brow * LDB + bcol]);
    }

    const __half* APh[3] = {A0, A1, A2};
    const __half* BPh[3] = {B0, B1, B2};
    const int nIter = nPhase * (K / 32);   // phase = i>>6, ktile = i&63

    auto issue = [&](int i) {
        const int ph = i >> 6;
        const int kt = (i & 63) * 32;
        const __half* ga = APh[ph] + (size_t)(m0 + arow) * K + acol + kt;
        const __half* gb = BPh[ph] + (size_t)(kt + brow) * N + n0 + bcol;
        const int b = i & 1;
        cpa16(sA[b],      ga);
        cpa16(sA[b] + 16, ga + 8);
        cpa16(sB[b],      gb);
        cpa16(sB[b] + 16, gb + 8);
        cpcommit();
    };

    issue(0);

    for (int i = 0; i < nIter; i++) {
        if (i + 1 < nIter) { issue(i + 1); cpwait<1>(); }
        else               { cpwait<0>(); }
        __syncthreads();

        const __half* as = As[i & 1];
        const __half* bs = Bs[i & 1];

        #pragma unroll
        for (int kk = 0; kk < 32; kk += 16) {
            unsigned a[2][4];
            #pragma unroll
            for (int mf = 0; mf < 2; mf++) {
                const __half* p = as + (wm * 32 + mf * 16 + (lane & 15)) * LDA
                                     + kk + (lane >> 4) * 8;
                ldmA(a[mf][0], a[mf][1], a[mf][2], a[mf][3], saddr(p));
            }
            unsigned bfr[8][2];
            #pragma unroll
            for (int nq = 0; nq < 4; nq++) {
                const __half* p = bs + (kk + (lane & 15)) * LDB
                                     + wn * 64 + nq * 16 + (lane >> 4) * 8;
                unsigned r0, r1, r2, r3;
                ldmBT(r0, r1, r2, r3, saddr(p));
                bfr[nq*2][0] = r0; bfr[nq*2][1] = r1;
                bfr[nq*2+1][0] = r2; bfr[nq*2+1][1] = r3;
            }
            #pragma unroll
            for (int mf = 0; mf < 2; mf++)
                #pragma unroll
                for (int nf = 0; nf < 8; nf++)
                    mma16816(d[mf][nf], a[mf], bfr[nf]);
        }

        // drain every 4 k-tiles: bound tensor-core truncation-bias chains
        if ((i & 3) == 3) {
            #pragma unroll
            for (int mf = 0; mf < 2; mf++)
                #pragma unroll
                for (int nf = 0; nf < 8; nf++)
                    #pragma unroll
                    for (int e = 0; e < 4; e++) {
                        sum[mf][nf][e] += d[mf][nf][e];
                        d[mf][nf][e] = 0.f;
                    }
        }
        __syncthreads();
    }

    // ---------------- epilogue ----------------
    const int lr = lane >> 2;
    const int lc = (lane & 3) * 2;
    #pragma unroll
    for (int mf = 0; mf < 2; mf++) {
        #pragma unroll
        for (int nf = 0; nf < 8; nf++) {
            float* dd = sum[mf][nf];
            const int row0 = m0 + wm * 32 + mf * 16 + lr;
            const int col  = n0 + wn * 64 + nf * 8 + lc;
            #pragma unroll
            for (int half = 0; half < 2; half++) {
                const int row = row0 + half * 8;
                const float e = dd[half*2], o = dd[half*2 + 1];
                if (MODE == 3) {
                    *reinterpret_cast<float2*>(outF + (size_t)row * N + col) =
                        make_float2(e, o);
                } else {
                    const int b = row >> 11, s = row & (Sn - 1);
                    const int h = col >> 7, jd = col & (DHn - 1);
                    bf16* dst = (MODE == 0) ? g_Q : (MODE == 1) ? g_K : g_V;
                    bf162 val;
                    if (MODE == 2) {
                        val.x = __float2bfloat16(e);
                        val.y = __float2bfloat16(o);
                    } else {
                        float2 cssn = g_rope[s * 64 + (jd >> 1)];
                        val.x = __float2bfloat16(e * cssn.x - o * cssn.y);
                        val.y = __float2bfloat16(e * cssn.y + o * cssn.x);
                    }
                    *reinterpret_cast<bf162*>(
                        dst + ((size_t)(b * Hn + h) * Sn + s) * DHn + jd) = val;
                }
            }
        }
    }
}

// ============================================================
// Two-pass causal flash attention (scalar; known-good numerics)
// ============================================================
__device__ __forceinline__ float dot32(const float* qv, const bf16* kp) {
    const uint4* kr = reinterpret_cast<const uint4*>(kp);
    float x = 0.f;
    #pragma unroll
    for (int c = 0; c < 4; c++) {
        uint4 u = kr[c];
        float2 f;
        f = bf2x(u.x); x = fmaf(qv[c*8+0], f.x, x); x = fmaf(qv[c*8+1], f.y, x);
        f = bf2x(u.y); x = fmaf(qv[c*8+2], f.x, x); x = fmaf(qv[c*8+3], f.y, x);
        f = bf2x(u.z); x = fmaf(qv[c*8+4], f.x, x); x = fmaf(qv[c*8+5], f.y, x);
        f = bf2x(u.w); x = fmaf(qv[c*8+6], f.x, x); x = fmaf(qv[c*8+7], f.y, x);
    }
    return x;
}

__global__ void __launch_bounds__(128)
flash_kernel()
{
    __shared__ bf16 Ks[64][DHn];
    __shared__ bf16 Vs[64][DHn];

    const int tid  = threadIdx.x;
    const int bh   = blockIdx.y;
    const int q0   = blockIdx.x * 32;
    const int qrow = q0 + (tid >> 2);
    const int sl   = (tid & 3) * 32;

    float qv[32];
    {
        const uint4* qp = reinterpret_cast<const uint4*>(
            g_Q + ((size_t)bh * Sn + qrow) * DHn + sl);
        #pragma unroll
        for (int c = 0; c < 4; c++) {
            uint4 u = qp[c];
            float2 f;
            f = bf2x(u.x); qv[c*8+0] = f.x; qv[c*8+1] = f.y;
            f = bf2x(u.y); qv[c*8+2] = f.x; qv[c*8+3] = f.y;
            f = bf2x(u.z); qv[c*8+4] = f.x; qv[c*8+5] = f.y;
            f = bf2x(u.w); qv[c*8+6] = f.x; qv[c*8+7] = f.y;
        }
    }

    const int nT = (q0 + 32 + 63) / 64;
    const float scale = 0.08838834764831845f;

    const uint4* Kg = reinterpret_cast<const uint4*>(g_K + (size_t)bh * Sn * DHn);
    const uint4* Vg = reinterpret_cast<const uint4*>(g_V + (size_t)bh * Sn * DHn);
    uint4* KsV = reinterpret_cast<uint4*>(&Ks[0][0]);
    uint4* VsV = reinterpret_cast<uint4*>(&Vs[0][0]);

    float m = -INFINITY, l = 0.f;
    for (int kt = 0; kt < nT; kt++) {
        for (int i2 = tid; i2 < 1024; i2 += 128) KsV[i2] = Kg[kt * 1024 + i2];
        __syncthreads();
        const bool full = (kt * 64 + 63 <= qrow);
        if (full) {
            #pragma unroll 4
            for (int kk = 0; kk < 64; kk++) {
                float sc = dot32(qv, &Ks[kk][sl]);
                sc += __shfl_xor_sync(0xffffffffu, sc, 1);
                sc += __shfl_xor_sync(0xffffffffu, sc, 2);
                sc *= scale;
                float mn = fmaxf(m, sc);
                l = l * __expf(m - mn) + __expf(sc - mn);
                m = mn;
            }
        } else {
            #pragma unroll 4
            for (int kk = 0; kk < 64; kk++) {
                float sc = dot32(qv, &Ks[kk][sl]);
                sc += __shfl_xor_sync(0xffffffffu, sc, 1);
                sc += __shfl_xor_sync(0xffffffffu, sc, 2);
                sc *= scale;
                int key = kt * 64 + kk;
                if (key <= qrow) {
                    float mn = fmaxf(m, sc);
                    l = l * __expf(m - mn) + __expf(sc - mn);
                    m = mn;
                }
            }
        }
        __syncthreads();
    }
    const float inv_l = 1.0f / l;

    float acc[32];
    #pragma unroll
    for (int i = 0; i < 32; i++) acc[i] = 0.f;

    for (int kt = 0; kt < nT; kt++) {
        for (int i2 = tid; i2 < 1024; i2 += 128) {
            KsV[i2] = Kg[kt * 1024 + i2];
            VsV[i2] = Vg[kt * 1024 + i2];
        }
        __syncthreads();
        #pragma unroll 2
        for (int kk = 0; kk < 64; kk++) {
            float sc = dot32(qv, &Ks[kk][sl]);
            sc += __shfl_xor_sync(0xffffffffu, sc, 1);
            sc += __shfl_xor_sync(0xffffffffu, sc, 2);
            sc *= scale;
            int key = kt * 64 + kk;
            if (key <= qrow) {
                float p  = __expf(sc - m) * inv_l;
                float pf = __bfloat162float(__float2bfloat16(p));
                const uint4* vr = reinterpret_cast<const uint4*>(&Vs[kk][sl]);
                #pragma unroll
                for (int c = 0; c < 4; c++) {
                    uint4 u = vr[c];
                    float2 f;
                    f = bf2x(u.x); acc[c*8+0]=fmaf(pf,f.x,acc[c*8+0]); acc[c*8+1]=fmaf(pf,f.y,acc[c*8+1]);
                    f = bf2x(u.y); acc[c*8+2]=fmaf(pf,f.x,acc[c*8+2]); acc[c*8+3]=fmaf(pf,f.y,acc[c*8+3]);
                    f = bf2x(u.z); acc[c*8+4]=fmaf(pf,f.x,acc[c*8+4]); acc[c*8+5]=fmaf(pf,f.y,acc[c*8+5]);
                    f = bf2x(u.w); acc[c*8+6]=fmaf(pf,f.x,acc[c*8+6]); acc[c*8+7]=fmaf(pf,f.y,acc[c*8+7]);
                }
            }
        }
        __syncthreads();
    }

    // write attn rounded through bf16 (matching reference), stored as fp16 (exact)
    const int b = bh >> 4, h = bh & 15;
    __half* dst = g_attnb + ((size_t)(b * Sn + qrow)) * Dn + h * DHn + sl;
    #pragma unroll
    for (int i = 0; i < 32; i += 2) {
        __half2 v2;
        v2.x = __float2half(__bfloat162float(__float2bfloat16(acc[i])));
        v2.y = __float2half(__bfloat162float(__float2bfloat16(acc[i+1])));
        *reinterpret_cast<__half2*>(dst + i) = v2;
    }
}

// ============================================================
extern "C" void kernel_launch(void* const* d_in, const int* in_sizes, int n_in,
                              void* d_out, int out_size)
{
    const float* x  = (const float*)d_in[0];
    const float* w[4] = {(const float*)d_in[1], (const float*)d_in[2],
                         (const float*)d_in[3], (const float*)d_in[4]};
    float* out = (float*)d_out;

    __half *xhi, *xlo, *whi[4], *wlo[4], *attnb;
    cudaGetSymbolAddress((void**)&xhi, g_xhi);
    cudaGetSymbolAddress((void**)&xlo, g_xlo);
    cudaGetSymbolAddress((void**)&attnb, g_attnb);
    {
        __half *base_hi, *base_lo;
        cudaGetSymbolAddress((void**)&base_hi, g_whi);
        cudaGetSymbolAddress((void**)&base_lo, g_wlo);
        for (int i = 0; i < 4; i++) {
            whi[i] = base_hi + (size_t)i * Dn * Dn;
            wlo[i] = base_lo + (size_t)i * Dn * Dn;
        }
    }

    // split inputs into fp16 hi/lo
    {
        int n4 = Mn * Dn / 4;
        split_kernel<<<(n4 + 255) / 256, 256>>>(x, xhi, xlo, n4);
        int m4 = Dn * Dn / 4;
        for (int i = 0; i < 4; i++)
            split_kernel<<<(m4 + 255) / 256, 256>>>(w[i], whi[i], wlo[i], m4);
    }
    rope_tab_kernel<<<(Sn * 64 + 255) / 256, 256>>>();

    dim3 gg(Dn / 128, Mn / 128);
    // Q/K/V: A@B = xhi@whi + xlo@whi + xhi@wlo
    gemm_mma<0><<<gg, 256>>>(xhi, whi[0], xlo, whi[0], xhi, wlo[0], 3, nullptr);
    gemm_mma<1><<<gg, 256>>>(xhi, whi[1], xlo, whi[1], xhi, wlo[1], 3, nullptr);
    gemm_mma<2><<<gg, 256>>>(xhi, whi[2], xlo, whi[2], xhi, wlo[2], 3, nullptr);

    flash_kernel<<<dim3(Sn / 32, Bn * Hn), 128>>>();

    // out = attnb @ wo   (attnb exact, wo split -> 2 phases)
    gemm_mma<3><<<gg, 256>>>(attnb, whi[3], attnb, wlo[3], nullptr, nullptr, 2, out);
}

// round 7
// speedup vs baseline: 1.3521x; 1.0556x over previous
#include <cuda_runtime.h>
#include <cuda_bf16.h>
#include <cuda_fp16.h>
#include <math.h>
#include <stdint.h>

// Problem dims
#define Bn  2
#define Sn  2048
#define Dn  2048
#define Hn  16
#define DHn 128
#define Mn  (Bn*Sn)   // 4096

typedef __nv_bfloat16 bf16;
typedef __nv_bfloat162 bf162;

// ---------------- scratch (device globals; no allocation allowed) ----------
__device__ __half g_xhi[(size_t)Mn*Dn];
__device__ __half g_xlo[(size_t)Mn*Dn];
__device__ __half g_whi[4][(size_t)Dn*Dn];   // wq, wk, wv, wo
__device__ __half g_wlo[4][(size_t)Dn*Dn];
__device__ bf16 g_Q[(size_t)Bn*Hn*Sn*DHn];   // [b,h,s,dh]
__device__ bf16 g_K[(size_t)Bn*Hn*Sn*DHn];
__device__ bf16 g_V[(size_t)Bn*Hn*Sn*DHn];
__device__ __half g_attnb[(size_t)Mn*Dn];    // [b,s,d] fp16 (holds exact bf16 values)
__device__ float2 g_rope[(size_t)Sn*64];     // (cos, sin)

__device__ __forceinline__ float2 bf2x(unsigned w) {
    bf162 h = *reinterpret_cast<bf162*>(&w);
    return __bfloat1622float2(h);
}
__device__ __forceinline__ unsigned saddr(const void* p) {
    return (unsigned)__cvta_generic_to_shared(p);
}

// ---------------- cp.async helpers -----------------------------------------
__device__ __forceinline__ void cpa16(unsigned s, const void* g) {
    asm volatile("cp.async.cg.shared.global [%0], [%1], 16;\n" :: "r"(s), "l"(g));
}
__device__ __forceinline__ void cpcommit() {
    asm volatile("cp.async.commit_group;\n" ::);
}
template<int NW> __device__ __forceinline__ void cpwait() {
    asm volatile("cp.async.wait_group %0;\n" :: "n"(NW));
}

// ---------------- helpers ---------------------------------------------------
__global__ void split_kernel(const float* __restrict__ s,
                             __half* __restrict__ hi, __half* __restrict__ lo, int n4)
{
    int i = blockIdx.x * blockDim.x + threadIdx.x;
    if (i >= n4) return;
    float4 v = reinterpret_cast<const float4*>(s)[i];
    __half h0 = __float2half(v.x), h1 = __float2half(v.y);
    __half h2 = __float2half(v.z), h3 = __float2half(v.w);
    __half2 H0; H0.x = h0; H0.y = h1;
    __half2 H1; H1.x = h2; H1.y = h3;
    reinterpret_cast<__half2*>(hi)[2*i]   = H0;
    reinterpret_cast<__half2*>(hi)[2*i+1] = H1;
    __half2 L0, L1;
    L0.x = __float2half(v.x - __half2float(h0));
    L0.y = __float2half(v.y - __half2float(h1));
    L1.x = __float2half(v.z - __half2float(h2));
    L1.y = __float2half(v.w - __half2float(h3));
    reinterpret_cast<__half2*>(lo)[2*i]   = L0;
    reinterpret_cast<__half2*>(lo)[2*i+1] = L1;
}

__global__ void rope_tab_kernel()
{
    int idx = blockIdx.x * blockDim.x + threadIdx.x;   // s*64 + i
    if (idx >= Sn * 64) return;
    int s = idx >> 6, i = idx & 63;
    const float LOG1E4 = 9.210340371976184f;
    float inv = expf(-((float)(2 * i) / 128.0f) * LOG1E4);
    float ang = (float)s * inv;
    float sn, cs;
    sincosf(ang, &sn, &cs);
    g_rope[idx] = make_float2(cs, sn);
}

// ---------------- mma primitives -------------------------------------------
__device__ __forceinline__ void ldmA(unsigned &r0, unsigned &r1, unsigned &r2, unsigned &r3, unsigned a) {
    asm volatile("ldmatrix.sync.aligned.m8n8.x4.shared.b16 {%0,%1,%2,%3}, [%4];"
                 : "=r"(r0), "=r"(r1), "=r"(r2), "=r"(r3) : "r"(a));
}
__device__ __forceinline__ void ldmBT(unsigned &r0, unsigned &r1, unsigned &r2, unsigned &r3, unsigned a) {
    asm volatile("ldmatrix.sync.aligned.m8n8.x4.trans.shared.b16 {%0,%1,%2,%3}, [%4];"
                 : "=r"(r0), "=r"(r1), "=r"(r2), "=r"(r3) : "r"(a));
}
__device__ __forceinline__ void mma16816(float* d, const unsigned* a, const unsigned* b) {
    asm volatile("mma.sync.aligned.m16n8k16.row.col.f32.f16.f16.f32 "
                 "{%0,%1,%2,%3}, {%4,%5,%6,%7}, {%8,%9}, {%0,%1,%2,%3};"
                 : "+f"(d[0]), "+f"(d[1]), "+f"(d[2]), "+f"(d[3])
                 : "r"(a[0]), "r"(a[1]), "r"(a[2]), "r"(a[3]), "r"(b[0]), "r"(b[1]));
}

// ---------------- fp16 tensor-core GEMM, 3-stage cp.async, 1 sync/iter ------
// KIND 0 (QKV fused): grid.x = 48; which = blockIdx.x>>4 selects wq/wk/wv and
//   epilogue (0: rope->g_Q, 1: rope->g_K, 2: ->g_V). 3 split-phases.
// KIND 1 (out proj): grid.x = 16; 2 split-phases; writes f32 to outF.
// Accumulator drained to fp32 every 4 k-tiles (HMMA chain-bias suppression).
constexpr int LDA = 40, LDB = 136;
constexpr int A_STG = 128 * LDA;     // halves per A stage
constexpr int B_STG = 32 * LDB;      // halves per B stage
constexpr int SMEM_BYTES = 3 * (A_STG + B_STG) * 2;   // 56,832

template<int KIND>
__global__ void __launch_bounds__(256)
gemm_mma(const __half* __restrict__ a_hi, const __half* __restrict__ a_lo,
         const __half* __restrict__ w_hi, const __half* __restrict__ w_lo,
         float* __restrict__ outF)
{
    constexpr int K = Dn, N = Dn;
    extern __shared__ __half smem[];
    __half* AsBase = smem;
    __half* BsBase = smem + 3 * A_STG;

    const int tid = threadIdx.x;
    const int wid = tid >> 5, lane = tid & 31;
    const int wm = wid & 3, wn = wid >> 2;       // 4 x 2 warps
    const int m0 = blockIdx.y * 128;

    int mode, n0, nPhase;
    const __half *APh[3], *BPh[3];
    if (KIND == 0) {
        const int which = blockIdx.x >> 4;
        mode = which;
        n0 = (blockIdx.x & 15) * 128;
        const __half* W1 = w_hi + (size_t)which * Dn * Dn;
        const __half* W2 = w_lo + (size_t)which * Dn * Dn;
        APh[0] = a_hi; APh[1] = a_lo; APh[2] = a_hi;
        BPh[0] = W1;   BPh[1] = W1;   BPh[2] = W2;
        nPhase = 3;
    } else {
        mode = 3;
        n0 = blockIdx.x * 128;
        APh[0] = a_hi; APh[1] = a_hi; APh[2] = a_hi;
        BPh[0] = w_hi; BPh[1] = w_lo; BPh[2] = w_lo;
        nPhase = 2;
    }
    const int nIter = nPhase * (K / 32);   // phase = i>>6, ktile = i&63

    float d[2][8][4];     // HMMA accumulator (short chains)
    float sum[2][8][4];   // fp32 master accumulator (RN adds)
    #pragma unroll
    for (int mf = 0; mf < 2; mf++)
        #pragma unroll
        for (int nf = 0; nf < 8; nf++)
            #pragma unroll
            for (int e = 0; e < 4; e++) { d[mf][nf][e] = 0.f; sum[mf][nf][e] = 0.f; }

    // loading layout: A 32B/thread/tile, B 32B/thread/tile
    const int arow = tid >> 1, acol = (tid & 1) * 16;
    const int brow = tid >> 3, bcol = (tid & 7) * 16;

    unsigned sA[3], sB[3];
    #pragma unroll
    for (int b = 0; b < 3; b++) {
        sA[b] = saddr(AsBase + b * A_STG + arow * LDA + acol);
        sB[b] = saddr(BsBase + b * B_STG + brow * LDB + bcol);
    }

    auto issue = [&](int i) {
        const int ph = i >> 6;
        const int kt = (i & 63) * 32;
        const __half* ga = APh[ph] + (size_t)(m0 + arow) * K + acol + kt;
        const __half* gb = BPh[ph] + (size_t)(kt + brow) * N + n0 + bcol;
        const int b = i % 3;
        cpa16(sA[b],      ga);
        cpa16(sA[b] + 16, ga + 8);
        cpa16(sB[b],      gb);
        cpa16(sB[b] + 16, gb + 8);
        cpcommit();
    };

    issue(0);
    issue(1);

    for (int i = 0; i < nIter; i++) {
        if (i + 1 < nIter) cpwait<1>(); else cpwait<0>();
        __syncthreads();
        if (i + 2 < nIter) issue(i + 2);

        const int stg = i % 3;
        const __half* as = AsBase + stg * A_STG;
        const __half* bs = BsBase + stg * B_STG;

        #pragma unroll
        for (int kk = 0; kk < 32; kk += 16) {
            unsigned a[2][4];
            #pragma unroll
            for (int mf = 0; mf < 2; mf++) {
                const __half* p = as + (wm * 32 + mf * 16 + (lane & 15)) * LDA
                                     + kk + (lane >> 4) * 8;
                ldmA(a[mf][0], a[mf][1], a[mf][2], a[mf][3], saddr(p));
            }
            unsigned bfr[8][2];
            #pragma unroll
            for (int nq = 0; nq < 4; nq++) {
                const __half* p = bs + (kk + (lane & 15)) * LDB
                                     + wn * 64 + nq * 16 + (lane >> 4) * 8;
                unsigned r0, r1, r2, r3;
                ldmBT(r0, r1, r2, r3, saddr(p));
                bfr[nq*2][0] = r0; bfr[nq*2][1] = r1;
                bfr[nq*2+1][0] = r2; bfr[nq*2+1][1] = r3;
            }
            #pragma unroll
            for (int mf = 0; mf < 2; mf++)
                #pragma unroll
                for (int nf = 0; nf < 8; nf++)
                    mma16816(d[mf][nf], a[mf], bfr[nf]);
        }

        // drain every 4 k-tiles: bound tensor-core truncation-bias chains
        if ((i & 3) == 3) {
            #pragma unroll
            for (int mf = 0; mf < 2; mf++)
                #pragma unroll
                for (int nf = 0; nf < 8; nf++)
                    #pragma unroll
                    for (int e = 0; e < 4; e++) {
                        sum[mf][nf][e] += d[mf][nf][e];
                        d[mf][nf][e] = 0.f;
                    }
        }
    }

    // ---------------- epilogue ----------------
    const int lr = lane >> 2;
    const int lc = (lane & 3) * 2;
    #pragma unroll
    for (int mf = 0; mf < 2; mf++) {
        #pragma unroll
        for (int nf = 0; nf < 8; nf++) {
            float* dd = sum[mf][nf];
            const int row0 = m0 + wm * 32 + mf * 16 + lr;
            const int col  = n0 + wn * 64 + nf * 8 + lc;
            #pragma unroll
            for (int half = 0; half < 2; half++) {
                const int row = row0 + half * 8;
                const float e = dd[half*2], o = dd[half*2 + 1];
                if (KIND == 1) {
                    *reinterpret_cast<float2*>(outF + (size_t)row * N + col) =
                        make_float2(e, o);
                } else {
                    const int b = row >> 11, s = row & (Sn - 1);
                    const int h = col >> 7, jd = col & (DHn - 1);
                    bf16* dst = (mode == 0) ? g_Q : (mode == 1) ? g_K : g_V;
                    bf162 val;
                    if (mode == 2) {
                        val.x = __float2bfloat16(e);
                        val.y = __float2bfloat16(o);
                    } else {
                        float2 cssn = g_rope[s * 64 + (jd >> 1)];
                        val.x = __float2bfloat16(e * cssn.x - o * cssn.y);
                        val.y = __float2bfloat16(e * cssn.y + o * cssn.x);
                    }
                    *reinterpret_cast<bf162*>(
                        dst + ((size_t)(b * Hn + h) * Sn + s) * DHn + jd) = val;
                }
            }
        }
    }
}

// ============================================================
// Two-pass causal flash attention (scalar; known-good numerics)
// ============================================================
__device__ __forceinline__ float dot32(const float* qv, const bf16* kp) {
    const uint4* kr = reinterpret_cast<const uint4*>(kp);
    float x = 0.f;
    #pragma unroll
    for (int c = 0; c < 4; c++) {
        uint4 u = kr[c];
        float2 f;
        f = bf2x(u.x); x = fmaf(qv[c*8+0], f.x, x); x = fmaf(qv[c*8+1], f.y, x);
        f = bf2x(u.y); x = fmaf(qv[c*8+2], f.x, x); x = fmaf(qv[c*8+3], f.y, x);
        f = bf2x(u.z); x = fmaf(qv[c*8+4], f.x, x); x = fmaf(qv[c*8+5], f.y, x);
        f = bf2x(u.w); x = fmaf(qv[c*8+6], f.x, x); x = fmaf(qv[c*8+7], f.y, x);
    }
    return x;
}

__global__ void __launch_bounds__(128)
flash_kernel()
{
    __shared__ bf16 Ks[64][DHn];
    __shared__ bf16 Vs[64][DHn];

    const int tid  = threadIdx.x;
    const int bh   = blockIdx.y;
    const int q0   = blockIdx.x * 32;
    const int qrow = q0 + (tid >> 2);
    const int sl   = (tid & 3) * 32;

    float qv[32];
    {
        const uint4* qp = reinterpret_cast<const uint4*>(
            g_Q + ((size_t)bh * Sn + qrow) * DHn + sl);
        #pragma unroll
        for (int c = 0; c < 4; c++) {
            uint4 u = qp[c];
            float2 f;
            f = bf2x(u.x); qv[c*8+0] = f.x; qv[c*8+1] = f.y;
            f = bf2x(u.y); qv[c*8+2] = f.x; qv[c*8+3] = f.y;
            f = bf2x(u.z); qv[c*8+4] = f.x; qv[c*8+5] = f.y;
            f = bf2x(u.w); qv[c*8+6] = f.x; qv[c*8+7] = f.y;
        }
    }

    const int nT = (q0 + 32 + 63) / 64;
    const float scale = 0.08838834764831845f;

    const uint4* Kg = reinterpret_cast<const uint4*>(g_K + (size_t)bh * Sn * DHn);
    const uint4* Vg = reinterpret_cast<const uint4*>(g_V + (size_t)bh * Sn * DHn);
    uint4* KsV = reinterpret_cast<uint4*>(&Ks[0][0]);
    uint4* VsV = reinterpret_cast<uint4*>(&Vs[0][0]);

    float m = -INFINITY, l = 0.f;
    for (int kt = 0; kt < nT; kt++) {
        for (int i2 = tid; i2 < 1024; i2 += 128) KsV[i2] = Kg[kt * 1024 + i2];
        __syncthreads();
        const bool full = (kt * 64 + 63 <= qrow);
        if (full) {
            #pragma unroll 4
            for (int kk = 0; kk < 64; kk++) {
                float sc = dot32(qv, &Ks[kk][sl]);
                sc += __shfl_xor_sync(0xffffffffu, sc, 1);
                sc += __shfl_xor_sync(0xffffffffu, sc, 2);
                sc *= scale;
                float mn = fmaxf(m, sc);
                l = l * __expf(m - mn) + __expf(sc - mn);
                m = mn;
            }
        } else {
            #pragma unroll 4
            for (int kk = 0; kk < 64; kk++) {
                float sc = dot32(qv, &Ks[kk][sl]);
                sc += __shfl_xor_sync(0xffffffffu, sc, 1);
                sc += __shfl_xor_sync(0xffffffffu, sc, 2);
                sc *= scale;
                int key = kt * 64 + kk;
                if (key <= qrow) {
                    float mn = fmaxf(m, sc);
                    l = l * __expf(m - mn) + __expf(sc - mn);
                    m = mn;
                }
            }
        }
        __syncthreads();
    }
    const float inv_l = 1.0f / l;

    float acc[32];
    #pragma unroll
    for (int i = 0; i < 32; i++) acc[i] = 0.f;

    for (int kt = 0; kt < nT; kt++) {
        for (int i2 = tid; i2 < 1024; i2 += 128) {
            KsV[i2] = Kg[kt * 1024 + i2];
            VsV[i2] = Vg[kt * 1024 + i2];
        }
        __syncthreads();
        #pragma unroll 2
        for (int kk = 0; kk < 64; kk++) {
            float sc = dot32(qv, &Ks[kk][sl]);
            sc += __shfl_xor_sync(0xffffffffu, sc, 1);
            sc += __shfl_xor_sync(0xffffffffu, sc, 2);
            sc *= scale;
            int key = kt * 64 + kk;
            if (key <= qrow) {
                float p  = __expf(sc - m) * inv_l;
                float pf = __bfloat162float(__float2bfloat16(p));
                const uint4* vr = reinterpret_cast<const uint4*>(&Vs[kk][sl]);
                #pragma unroll
                for (int c = 0; c < 4; c++) {
                    uint4 u = vr[c];
                    float2 f;
                    f = bf2x(u.x); acc[c*8+0]=fmaf(pf,f.x,acc[c*8+0]); acc[c*8+1]=fmaf(pf,f.y,acc[c*8+1]);
                    f = bf2x(u.y); acc[c*8+2]=fmaf(pf,f.x,acc[c*8+2]); acc[c*8+3]=fmaf(pf,f.y,acc[c*8+3]);
                    f = bf2x(u.z); acc[c*8+4]=fmaf(pf,f.x,acc[c*8+4]); acc[c*8+5]=fmaf(pf,f.y,acc[c*8+5]);
                    f = bf2x(u.w); acc[c*8+6]=fmaf(pf,f.x,acc[c*8+6]); acc[c*8+7]=fmaf(pf,f.y,acc[c*8+7]);
                }
            }
        }
        __syncthreads();
    }

    // write attn rounded through bf16 (matching reference), stored as fp16 (exact)
    const int b = bh >> 4, h = bh & 15;
    __half* dst = g_attnb + ((size_t)(b * Sn + qrow)) * Dn + h * DHn + sl;
    #pragma unroll
    for (int i = 0; i < 32; i += 2) {
        __half2 v2;
        v2.x = __float2half(__bfloat162float(__float2bfloat16(acc[i])));
        v2.y = __float2half(__bfloat162float(__float2bfloat16(acc[i+1])));
        *reinterpret_cast<__half2*>(dst + i) = v2;
    }
}

// ============================================================
extern "C" void kernel_launch(void* const* d_in, const int* in_sizes, int n_in,
                              void* d_out, int out_size)
{
    const float* x  = (const float*)d_in[0];
    const float* w[4] = {(const float*)d_in[1], (const float*)d_in[2],
                         (const float*)d_in[3], (const float*)d_in[4]};
    float* out = (float*)d_out;

    __half *xhi, *xlo, *whiB, *wloB, *attnb;
    cudaGetSymbolAddress((void**)&xhi, g_xhi);
    cudaGetSymbolAddress((void**)&xlo, g_xlo);
    cudaGetSymbolAddress((void**)&attnb, g_attnb);
    cudaGetSymbolAddress((void**)&whiB, g_whi);
    cudaGetSymbolAddress((void**)&wloB, g_wlo);

    cudaFuncSetAttribute(gemm_mma<0>, cudaFuncAttributeMaxDynamicSharedMemorySize, SMEM_BYTES);
    cudaFuncSetAttribute(gemm_mma<1>, cudaFuncAttributeMaxDynamicSharedMemorySize, SMEM_BYTES);

    // split inputs into fp16 hi/lo
    {
        int n4 = Mn * Dn / 4;
        split_kernel<<<(n4 + 255) / 256, 256>>>(x, xhi, xlo, n4);
        int m4 = Dn * Dn / 4;
        for (int i = 0; i < 4; i++)
            split_kernel<<<(m4 + 255) / 256, 256>>>(
                w[i], whiB + (size_t)i * Dn * Dn, wloB + (size_t)i * Dn * Dn, m4);
    }
    rope_tab_kernel<<<(Sn * 64 + 255) / 256, 256>>>();

    // fused QKV projection (rope + bf16 epilogues)
    gemm_mma<0><<<dim3(48, Mn / 128), 256, SMEM_BYTES>>>(xhi, xlo, whiB, wloB, nullptr);

    flash_kernel<<<dim3(Sn / 32, Bn * Hn), 128>>>();

    // out = attnb @ wo   (attnb exact fp16, wo split -> 2 phases)
    gemm_mma<1><<<dim3(16, Mn / 128), 256, SMEM_BYTES>>>(
        attnb, nullptr, whiB + (size_t)3 * Dn * Dn, wloB + (size_t)3 * Dn * Dn, out);
}

// round 8
// speedup vs baseline: 3.2718x; 2.4197x over previous
#include <cuda_runtime.h>
#include <cuda_bf16.h>
#include <cuda_fp16.h>
#include <math.h>
#include <stdint.h>

// Problem dims
#define Bn  2
#define Sn  2048
#define Dn  2048
#define Hn  16
#define DHn 128
#define Mn  (Bn*Sn)   // 4096

typedef __nv_bfloat16 bf16;
typedef __nv_bfloat162 bf162;

// ---------------- scratch (device globals; no allocation allowed) ----------
__device__ __half g_xhi[(size_t)Mn*Dn];
__device__ __half g_xlo[(size_t)Mn*Dn];
__device__ __half g_whi[4][(size_t)Dn*Dn];   // wq, wk, wv, wo
__device__ __half g_wlo[4][(size_t)Dn*Dn];
__device__ bf16 g_Q[(size_t)Bn*Hn*Sn*DHn];   // [b,h,s,dh]
__device__ bf16 g_K[(size_t)Bn*Hn*Sn*DHn];
__device__ bf16 g_V[(size_t)Bn*Hn*Sn*DHn];
__device__ __half g_attnb[(size_t)Mn*Dn];    // [b,s,d] fp16 (holds exact bf16 values)
__device__ float2 g_rope[(size_t)Sn*64];     // (cos, sin)

__device__ __forceinline__ unsigned saddr(const void* p) {
    return (unsigned)__cvta_generic_to_shared(p);
}

// ---------------- cp.async helpers -----------------------------------------
__device__ __forceinline__ void cpa16(unsigned s, const void* g) {
    asm volatile("cp.async.cg.shared.global [%0], [%1], 16;\n" :: "r"(s), "l"(g));
}
__device__ __forceinline__ void cpcommit() {
    asm volatile("cp.async.commit_group;\n" ::);
}
template<int NW> __device__ __forceinline__ void cpwait() {
    asm volatile("cp.async.wait_group %0;\n" :: "n"(NW));
}

// ---------------- helpers ---------------------------------------------------
__global__ void split_kernel(const float* __restrict__ s,
                             __half* __restrict__ hi, __half* __restrict__ lo, int n4)
{
    int i = blockIdx.x * blockDim.x + threadIdx.x;
    if (i >= n4) return;
    float4 v = reinterpret_cast<const float4*>(s)[i];
    __half h0 = __float2half(v.x), h1 = __float2half(v.y);
    __half h2 = __float2half(v.z), h3 = __float2half(v.w);
    __half2 H0; H0.x = h0; H0.y = h1;
    __half2 H1; H1.x = h2; H1.y = h3;
    reinterpret_cast<__half2*>(hi)[2*i]   = H0;
    reinterpret_cast<__half2*>(hi)[2*i+1] = H1;
    __half2 L0, L1;
    L0.x = __float2half(v.x - __half2float(h0));
    L0.y = __float2half(v.y - __half2float(h1));
    L1.x = __float2half(v.z - __half2float(h2));
    L1.y = __float2half(v.w - __half2float(h3));
    reinterpret_cast<__half2*>(lo)[2*i]   = L0;
    reinterpret_cast<__half2*>(lo)[2*i+1] = L1;
}

__global__ void rope_tab_kernel()
{
    int idx = blockIdx.x * blockDim.x + threadIdx.x;   // s*64 + i
    if (idx >= Sn * 64) return;
    int s = idx >> 6, i = idx & 63;
    const float LOG1E4 = 9.210340371976184f;
    float inv = expf(-((float)(2 * i) / 128.0f) * LOG1E4);
    float ang = (float)s * inv;
    float sn, cs;
    sincosf(ang, &sn, &cs);
    g_rope[idx] = make_float2(cs, sn);
}

// ---------------- mma primitives -------------------------------------------
__device__ __forceinline__ void ldmA(unsigned &r0, unsigned &r1, unsigned &r2, unsigned &r3, unsigned a) {
    asm volatile("ldmatrix.sync.aligned.m8n8.x4.shared.b16 {%0,%1,%2,%3}, [%4];"
                 : "=r"(r0), "=r"(r1), "=r"(r2), "=r"(r3) : "r"(a));
}
__device__ __forceinline__ void ldmBT(unsigned &r0, unsigned &r1, unsigned &r2, unsigned &r3, unsigned a) {
    asm volatile("ldmatrix.sync.aligned.m8n8.x4.trans.shared.b16 {%0,%1,%2,%3}, [%4];"
                 : "=r"(r0), "=r"(r1), "=r"(r2), "=r"(r3) : "r"(a));
}
__device__ __forceinline__ void mma16816(float* d, const unsigned* a, const unsigned* b) {
    asm volatile("mma.sync.aligned.m16n8k16.row.col.f32.f16.f16.f32 "
                 "{%0,%1,%2,%3}, {%4,%5,%6,%7}, {%8,%9}, {%0,%1,%2,%3};"
                 : "+f"(d[0]), "+f"(d[1]), "+f"(d[2]), "+f"(d[3])
                 : "r"(a[0]), "r"(a[1]), "r"(a[2]), "r"(a[3]), "r"(b[0]), "r"(b[1]));
}
__device__ __forceinline__ void mma16816bf(float* d, const unsigned* a, const unsigned* b) {
    asm volatile("mma.sync.aligned.m16n8k16.row.col.f32.bf16.bf16.f32 "
                 "{%0,%1,%2,%3}, {%4,%5,%6,%7}, {%8,%9}, {%0,%1,%2,%3};"
                 : "+f"(d[0]), "+f"(d[1]), "+f"(d[2]), "+f"(d[3])
                 : "r"(a[0]), "r"(a[1]), "r"(a[2]), "r"(a[3]), "r"(b[0]), "r"(b[1]));
}

// ---------------- fp16 tensor-core GEMM, 3-stage cp.async, 1 sync/iter ------
constexpr int LDA = 40, LDB = 136;
constexpr int A_STG = 128 * LDA;     // halves per A stage
constexpr int B_STG = 32 * LDB;      // halves per B stage
constexpr int SMEM_BYTES = 3 * (A_STG + B_STG) * 2;   // 56,832

template<int KIND>
__global__ void __launch_bounds__(256)
gemm_mma(const __half* __restrict__ a_hi, const __half* __restrict__ a_lo,
         const __half* __restrict__ w_hi, const __half* __restrict__ w_lo,
         float* __restrict__ outF)
{
    constexpr int K = Dn, N = Dn;
    extern __shared__ __half smem[];
    __half* AsBase = smem;
    __half* BsBase = smem + 3 * A_STG;

    const int tid = threadIdx.x;
    const int wid = tid >> 5, lane = tid & 31;
    const int wm = wid & 3, wn = wid >> 2;       // 4 x 2 warps
    const int m0 = blockIdx.y * 128;

    int mode, n0, nPhase;
    const __half *APh[3], *BPh[3];
    if (KIND == 0) {
        const int which = blockIdx.x >> 4;
        mode = which;
        n0 = (blockIdx.x & 15) * 128;
        const __half* W1 = w_hi + (size_t)which * Dn * Dn;
        const __half* W2 = w_lo + (size_t)which * Dn * Dn;
        APh[0] = a_hi; APh[1] = a_lo; APh[2] = a_hi;
        BPh[0] = W1;   BPh[1] = W1;   BPh[2] = W2;
        nPhase = 3;
    } else {
        mode = 3;
        n0 = blockIdx.x * 128;
        APh[0] = a_hi; APh[1] = a_hi; APh[2] = a_hi;
        BPh[0] = w_hi; BPh[1] = w_lo; BPh[2] = w_lo;
        nPhase = 2;
    }
    const int nIter = nPhase * (K / 32);   // phase = i>>6, ktile = i&63

    float d[2][8][4];
    float sum[2][8][4];
    #pragma unroll
    for (int mf = 0; mf < 2; mf++)
        #pragma unroll
        for (int nf = 0; nf < 8; nf++)
            #pragma unroll
            for (int e = 0; e < 4; e++) { d[mf][nf][e] = 0.f; sum[mf][nf][e] = 0.f; }

    const int arow = tid >> 1, acol = (tid & 1) * 16;
    const int brow = tid >> 3, bcol = (tid & 7) * 16;

    unsigned sA[3], sB[3];
    #pragma unroll
    for (int b = 0; b < 3; b++) {
        sA[b] = saddr(AsBase + b * A_STG + arow * LDA + acol);
        sB[b] = saddr(BsBase + b * B_STG + brow * LDB + bcol);
    }

    auto issue = [&](int i) {
        const int ph = i >> 6;
        const int kt = (i & 63) * 32;
        const __half* ga = APh[ph] + (size_t)(m0 + arow) * K + acol + kt;
        const __half* gb = BPh[ph] + (size_t)(kt + brow) * N + n0 + bcol;
        const int b = i % 3;
        cpa16(sA[b],      ga);
        cpa16(sA[b] + 16, ga + 8);
        cpa16(sB[b],      gb);
        cpa16(sB[b] + 16, gb + 8);
        cpcommit();
    };

    issue(0);
    issue(1);

    for (int i = 0; i < nIter; i++) {
        if (i + 1 < nIter) cpwait<1>(); else cpwait<0>();
        __syncthreads();
        if (i + 2 < nIter) issue(i + 2);

        const int stg = i % 3;
        const __half* as = AsBase + stg * A_STG;
        const __half* bs = BsBase + stg * B_STG;

        #pragma unroll
        for (int kk = 0; kk < 32; kk += 16) {
            unsigned a[2][4];
            #pragma unroll
            for (int mf = 0; mf < 2; mf++) {
                const __half* p = as + (wm * 32 + mf * 16 + (lane & 15)) * LDA
                                     + kk + (lane >> 4) * 8;
                ldmA(a[mf][0], a[mf][1], a[mf][2], a[mf][3], saddr(p));
            }
            unsigned bfr[8][2];
            #pragma unroll
            for (int nq = 0; nq < 4; nq++) {
                const __half* p = bs + (kk + (lane & 15)) * LDB
                                     + wn * 64 + nq * 16 + (lane >> 4) * 8;
                unsigned r0, r1, r2, r3;
                ldmBT(r0, r1, r2, r3, saddr(p));
                bfr[nq*2][0] = r0; bfr[nq*2][1] = r1;
                bfr[nq*2+1][0] = r2; bfr[nq*2+1][1] = r3;
            }
            #pragma unroll
            for (int mf = 0; mf < 2; mf++)
                #pragma unroll
                for (int nf = 0; nf < 8; nf++)
                    mma16816(d[mf][nf], a[mf], bfr[nf]);
        }

        if ((i & 3) == 3) {
            #pragma unroll
            for (int mf = 0; mf < 2; mf++)
                #pragma unroll
                for (int nf = 0; nf < 8; nf++)
                    #pragma unroll
                    for (int e = 0; e < 4; e++) {
                        sum[mf][nf][e] += d[mf][nf][e];
                        d[mf][nf][e] = 0.f;
                    }
        }
    }

    const int lr = lane >> 2;
    const int lc = (lane & 3) * 2;
    #pragma unroll
    for (int mf = 0; mf < 2; mf++) {
        #pragma unroll
        for (int nf = 0; nf < 8; nf++) {
            float* dd = sum[mf][nf];
            const int row0 = m0 + wm * 32 + mf * 16 + lr;
            const int col  = n0 + wn * 64 + nf * 8 + lc;
            #pragma unroll
            for (int half = 0; half < 2; half++) {
                const int row = row0 + half * 8;
                const float e = dd[half*2], o = dd[half*2 + 1];
                if (KIND == 1) {
                    *reinterpret_cast<float2*>(outF + (size_t)row * N + col) =
                        make_float2(e, o);
                } else {
                    const int b = row >> 11, s = row & (Sn - 1);
                    const int h = col >> 7, jd = col & (DHn - 1);
                    bf16* dst = (mode == 0) ? g_Q : (mode == 1) ? g_K : g_V;
                    bf162 val;
                    if (mode == 2) {
                        val.x = __float2bfloat16(e);
                        val.y = __float2bfloat16(o);
                    } else {
                        float2 cssn = g_rope[s * 64 + (jd >> 1)];
                        val.x = __float2bfloat16(e * cssn.x - o * cssn.y);
                        val.y = __float2bfloat16(e * cssn.y + o * cssn.x);
                    }
                    *reinterpret_cast<bf162*>(
                        dst + ((size_t)(b * Hn + h) * Sn + s) * DHn + jd) = val;
                }
            }
        }
    }
}

// ============================================================
// Tensor-core two-pass causal flash attention.
// CTA: 128 threads (4 warps), 64 q-rows; warp w owns rows 16w..16w+15.
// Pass 1: S = Q K^T (bf16 mma), exact row max m and denom l (f32 exp).
// Pass 2: recompute S, p = bf16(exp(s-m)/l), PV via bf16 mma, drained
// into fp32 per k-tile (chain length 4).
// ============================================================
constexpr int FLD = 136;                 // smem row stride (halves)
constexpr int FTILE = 64 * FLD;          // halves per 64x128 tile
constexpr int FLASH_SMEM = 3 * FTILE * 2; // Q,K,V = 52,224 B

__global__ void __launch_bounds__(128)
flash_tc()
{
    extern __shared__ bf16 fs[];
    bf16* Qs = fs;
    bf16* Ks = fs + FTILE;
    bf16* Vs = fs + 2 * FTILE;

    const int tid  = threadIdx.x;
    const int warp = tid >> 5, lane = tid & 31;
    const int bh   = blockIdx.y;
    const int q0   = blockIdx.x * 64;
    const int nT   = blockIdx.x + 1;
    const float scale = 0.08838834764831845f;   // 1/sqrt(128)

    const bf16* Qg = g_Q + ((size_t)bh * Sn + q0) * DHn;
    const bf16* Kg = g_K + (size_t)bh * Sn * DHn;
    const bf16* Vg = g_V + (size_t)bh * Sn * DHn;

    const int lrow = tid & 63;            // tile row this thread loads
    const int lcb  = (tid >> 6) << 6;     // col block 0 / 64

    auto load_tile = [&](const bf16* g, bf16* s) {
        const bf16* gp = g + (size_t)lrow * DHn + lcb;
        unsigned sp = saddr(s + lrow * FLD + lcb);
        #pragma unroll
        for (int i = 0; i < 8; i++) cpa16(sp + i * 16, gp + i * 8);
    };

    // Q tile (stays resident)
    load_tile(Qg, Qs);
    cpcommit();

    const int lr = lane >> 2;             // fragment row within 16
    const int lc = (lane & 3) * 2;        // fragment col pair
    const int rA = q0 + warp * 16 + lr;   // global q row (half 0)
    const int rB = rA + 8;                // global q row (half 1)

    // S-fragment compute (shared by both passes)
    auto computeS = [&](float c[8][4], int kt) {
        #pragma unroll
        for (int nf = 0; nf < 8; nf++)
            #pragma unroll
            for (int e = 0; e < 4; e++) c[nf][e] = 0.f;
        #pragma unroll
        for (int ks = 0; ks < 8; ks++) {
            unsigned a[4];
            ldmA(a[0], a[1], a[2], a[3],
                 saddr(Qs + (warp * 16 + (lane & 15)) * FLD + ks * 16 + (lane >> 4) * 8));
            unsigned bk[8][2];
            #pragma unroll
            for (int nq = 0; nq < 4; nq++) {
                unsigned r0, r1, r2, r3;
                ldmA(r0, r1, r2, r3,
                     saddr(Ks + (nq * 16 + (lane & 15)) * FLD + ks * 16 + (lane >> 4) * 8));
                bk[nq*2][0]   = r0; bk[nq*2][1]   = r2;
                bk[nq*2+1][0] = r1; bk[nq*2+1][1] = r3;
            }
            #pragma unroll
            for (int nf = 0; nf < 8; nf++)
                mma16816bf(c[nf], a, bk[nf]);
        }
        // scale + causal mask (only diagonal tile partially masked)
        if (kt == nT - 1) {
            #pragma unroll
            for (int nf = 0; nf < 8; nf++) {
                const int col = kt * 64 + nf * 8 + lc;
                c[nf][0] = (col     <= rA) ? c[nf][0] * scale : -INFINITY;
                c[nf][1] = (col + 1 <= rA) ? c[nf][1] * scale : -INFINITY;
                c[nf][2] = (col     <= rB) ? c[nf][2] * scale : -INFINITY;
                c[nf][3] = (col + 1 <= rB) ? c[nf][3] * scale : -INFINITY;
            }
        } else {
            #pragma unroll
            for (int nf = 0; nf < 8; nf++)
                #pragma unroll
                for (int e = 0; e < 4; e++) c[nf][e] *= scale;
        }
    };

    // ---- pass 1: m, l ----
    float mA = -INFINITY, lA = 0.f, mB = -INFINITY, lB = 0.f;
    for (int kt = 0; kt < nT; kt++) {
        __syncthreads();
        load_tile(Kg + (size_t)kt * 64 * DHn, Ks);
        cpcommit();
        cpwait<0>();
        __syncthreads();

        float c[8][4];
        computeS(c, kt);

        float tA = -INFINITY, tB = -INFINITY;
        #pragma unroll
        for (int nf = 0; nf < 8; nf++) {
            tA = fmaxf(tA, fmaxf(c[nf][0], c[nf][1]));
            tB = fmaxf(tB, fmaxf(c[nf][2], c[nf][3]));
        }
        tA = fmaxf(tA, __shfl_xor_sync(0xffffffffu, tA, 1));
        tA = fmaxf(tA, __shfl_xor_sync(0xffffffffu, tA, 2));
        tB = fmaxf(tB, __shfl_xor_sync(0xffffffffu, tB, 1));
        tB = fmaxf(tB, __shfl_xor_sync(0xffffffffu, tB, 2));

        const float mnA = fmaxf(mA, tA), mnB = fmaxf(mB, tB);
        float sA = 0.f, sB = 0.f;
        #pragma unroll
        for (int nf = 0; nf < 8; nf++) {
            sA += __expf(c[nf][0] - mnA) + __expf(c[nf][1] - mnA);
            sB += __expf(c[nf][2] - mnB) + __expf(c[nf][3] - mnB);
        }
        sA += __shfl_xor_sync(0xffffffffu, sA, 1);
        sA += __shfl_xor_sync(0xffffffffu, sA, 2);
        sB += __shfl_xor_sync(0xffffffffu, sB, 1);
        sB += __shfl_xor_sync(0xffffffffu, sB, 2);

        lA = lA * __expf(mA - mnA) + sA; mA = mnA;
        lB = lB * __expf(mB - mnB) + sB; mB = mnB;
    }
    const float invA = 1.0f / lA, invB = 1.0f / lB;

    // ---- pass 2: O = bf16(p) V ----
    float o[16][4];
    #pragma unroll
    for (int nb = 0; nb < 16; nb++)
        #pragma unroll
        for (int e = 0; e < 4; e++) o[nb][e] = 0.f;

    for (int kt = 0; kt < nT; kt++) {
        __syncthreads();
        load_tile(Kg + (size_t)kt * 64 * DHn, Ks);
        load_tile(Vg + (size_t)kt * 64 * DHn, Vs);
        cpcommit();
        cpwait<0>();
        __syncthreads();

        float c[8][4];
        computeS(c, kt);

        unsigned pr[8][2];
        #pragma unroll
        for (int nf = 0; nf < 8; nf++) {
            bf162 v0, v1;
            v0.x = __float2bfloat16(__expf(c[nf][0] - mA) * invA);
            v0.y = __float2bfloat16(__expf(c[nf][1] - mA) * invA);
            v1.x = __float2bfloat16(__expf(c[nf][2] - mB) * invB);
            v1.y = __float2bfloat16(__expf(c[nf][3] - mB) * invB);
            pr[nf][0] = *reinterpret_cast<unsigned*>(&v0);
            pr[nf][1] = *reinterpret_cast<unsigned*>(&v1);
        }

        float d[16][4];
        #pragma unroll
        for (int nb = 0; nb < 16; nb++)
            #pragma unroll
            for (int e = 0; e < 4; e++) d[nb][e] = 0.f;

        #pragma unroll
        for (int kb = 0; kb < 4; kb++) {
            unsigned a[4] = {pr[2*kb][0], pr[2*kb][1], pr[2*kb+1][0], pr[2*kb+1][1]};
            unsigned bv[16][2];
            #pragma unroll
            for (int nbp = 0; nbp < 8; nbp++) {
                unsigned r0, r1, r2, r3;
                ldmBT(r0, r1, r2, r3,
                      saddr(Vs + (kb * 16 + (lane & 15)) * FLD + nbp * 16 + (lane >> 4) * 8));
                bv[nbp*2][0]   = r0; bv[nbp*2][1]   = r1;
                bv[nbp*2+1][0] = r2; bv[nbp*2+1][1] = r3;
            }
            #pragma unroll
            for (int nb = 0; nb < 16; nb++)
                mma16816bf(d[nb], a, bv[nb]);
        }
        #pragma unroll
        for (int nb = 0; nb < 16; nb++)
            #pragma unroll
            for (int e = 0; e < 4; e++) o[nb][e] += d[nb][e];
    }

    // epilogue: bf16-round, store fp16 to g_attnb [b,s,d]
    const int b = bh >> 4, h = bh & 15;
    #pragma unroll
    for (int nb = 0; nb < 16; nb++) {
        const int col = nb * 8 + lc;
        __half2 vA, vB;
        vA.x = __float2half(__bfloat162float(__float2bfloat16(o[nb][0])));
        vA.y = __float2half(__bfloat162float(__float2bfloat16(o[nb][1])));
        vB.x = __float2half(__bfloat162float(__float2bfloat16(o[nb][2])));
        vB.y = __float2half(__bfloat162float(__float2bfloat16(o[nb][3])));
        *reinterpret_cast<__half2*>(
            g_attnb + ((size_t)(b * Sn + rA)) * Dn + h * DHn + col) = vA;
        *reinterpret_cast<__half2*>(
            g_attnb + ((size_t)(b * Sn + rB)) * Dn + h * DHn + col) = vB;
    }
}

// ============================================================
extern "C" void kernel_launch(void* const* d_in, const int* in_sizes, int n_in,
                              void* d_out, int out_size)
{
    const float* x  = (const float*)d_in[0];
    const float* w[4] = {(const float*)d_in[1], (const float*)d_in[2],
                         (const float*)d_in[3], (const float*)d_in[4]};
    float* out = (float*)d_out;

    __half *xhi, *xlo, *whiB, *wloB, *attnb;
    cudaGetSymbolAddress((void**)&xhi, g_xhi);
    cudaGetSymbolAddress((void**)&xlo, g_xlo);
    cudaGetSymbolAddress((void**)&attnb, g_attnb);
    cudaGetSymbolAddress((void**)&whiB, g_whi);
    cudaGetSymbolAddress((void**)&wloB, g_wlo);

    cudaFuncSetAttribute(gemm_mma<0>, cudaFuncAttributeMaxDynamicSharedMemorySize, SMEM_BYTES);
    cudaFuncSetAttribute(gemm_mma<1>, cudaFuncAttributeMaxDynamicSharedMemorySize, SMEM_BYTES);
    cudaFuncSetAttribute(flash_tc, cudaFuncAttributeMaxDynamicSharedMemorySize, FLASH_SMEM);

    // split inputs into fp16 hi/lo
    {
        int n4 = Mn * Dn / 4;
        split_kernel<<<(n4 + 255) / 256, 256>>>(x, xhi, xlo, n4);
        int m4 = Dn * Dn / 4;
        for (int i = 0; i < 4; i++)
            split_kernel<<<(m4 + 255) / 256, 256>>>(
                w[i], whiB + (size_t)i * Dn * Dn, wloB + (size_t)i * Dn * Dn, m4);
    }
    rope_tab_kernel<<<(Sn * 64 + 255) / 256, 256>>>();

    // fused QKV projection (rope + bf16 epilogues)
    gemm_mma<0><<<dim3(48, Mn / 128), 256, SMEM_BYTES>>>(xhi, xlo, whiB, wloB, nullptr);

    flash_tc<<<dim3(Sn / 64, Bn * Hn), 128, FLASH_SMEM>>>();

    // out = attnb @ wo   (attnb exact fp16, wo split -> 2 phases)
    gemm_mma<1><<<dim3(16, Mn / 128), 256, SMEM_BYTES>>>(
        attnb, nullptr, whiB + (size_t)3 * Dn * Dn, wloB + (size_t)3 * Dn * Dn, out);
}